// round 9
// baseline (speedup 1.0000x reference)
#include <cuda_runtime.h>
#include <cuda_bf16.h>

#define NBINS 256
#define NIMG  96
#define BATCH 16            // 6 batches, double-buffered
#define HDIM  512
#define WDIM  512
#define CHUNK 16
#define PI_F  3.14159265358979323846f

#define TILES_PER_IMG (128 * 128)
#define BUF_FLOATS (4 * BATCH * TILES_PER_IMG * 4)   // 16.8 MB per buffer

#define HB_PER_BATCH (BATCH * 64)    // 1024 hist blocks per batch
#define MB_PER_BATCH (BATCH * 128)   // 2048 merge blocks per batch

// zero-initialized at load; merge restores owned regions to zero each call
// (block-exclusive coalesced stores) -> graph-replay safe.
__device__ float    g_buf[2][BUF_FLOATS];
__device__ unsigned g_vmax_u[NIMG];

__device__ __forceinline__ void red4(float* a, float x, float y, float z, float w) {
    asm volatile("red.global.add.v4.f32 [%0], {%1,%2,%3,%4};"
                 :: "l"(a), "f"(x), "f"(y), "f"(z), "f"(w) : "memory");
}

// ---------------------------------------------------------------------------
// hist block body: 64 blocks/image. One v4 red per pixel pair into parity
// copy c=(ia&1)*2+(ib&1), tile ((ia+1)>>1, (ib+1)>>1),
// lanes {wa0wb0, wa0wb1, wa1wb0, wa1wb1}. 256 threads.
// ---------------------------------------------------------------------------
__device__ __forceinline__ void hist_block(const float* __restrict__ X,
                                           float* __restrict__ buf,
                                           int img0, int hb) {
    const int img_l = hb >> 6;
    const int rest  = hb & 63;
    const int col   = ((rest & 1) << 8) + threadIdx.x;
    const int r0    = (rest >> 1) * CHUNK;

    const float* __restrict__ base =
        X + (size_t)(img0 + img_l) * (HDIM * WDIM) + col;

    float a  = __ldg(base + (size_t)r0 * WDIM);
    float fa = fminf(floorf(a), 254.0f);
    int   ia = (int)fa;
    float wa0 = 0.5f * (1.0f + __cosf(PI_F * (a - fa)));

    const int rmax = min(r0 + CHUNK, HDIM - 1);
    for (int r = r0; r < rmax; ++r) {
        float b  = __ldg(base + (size_t)(r + 1) * WDIM);
        float fb = fminf(floorf(b), 254.0f);
        int   ib = (int)fb;
        float wb0 = 0.5f * (1.0f + __cosf(PI_F * (b - fb)));

        const float wa1 = 1.0f - wa0;
        const float wb1 = 1.0f - wb0;

        const int c  = ((ia & 1) << 1) | (ib & 1);
        const int tr = (ia + 1) >> 1;
        const int tc = (ib + 1) >> 1;
        float* p = buf + ((((c * BATCH + img_l) << 14) + (tr << 7) + tc) << 2);
        red4(p, wa0 * wb0, wa0 * wb1, wa1 * wb0, wa1 * wb1);

        a = b; ia = ib; wa0 = wb0;
    }
}

// ---------------------------------------------------------------------------
// merge block body: 128 blocks/image, 256 threads, 2 bins/thread.
// Gathers 4 parity contributions, writes out (float2), self-zeroes its
// block-exclusive scratch region with coalesced float4/float2 stores,
// folds block max into g_vmax_u.
// ---------------------------------------------------------------------------
__device__ __forceinline__ void merge_block(float* __restrict__ buf,
                                            float* __restrict__ out,
                                            int img0, int mb) {
    const int img_l = mb >> 7;
    const int bx    = mb & 127;
    const int t     = threadIdx.x;
    const int di    = t >> 7;
    const int jp    = t & 127;            // column pair j' -> bins 2j', 2j'+1
    const int i     = (bx << 1) + di;

    const float2* __restrict__ buf2 = reinterpret_cast<const float2*>(buf);

    float s0 = 0.0f, s1 = 0.0f;
    #pragma unroll
    for (int pr = 0; pr < 2; ++pr) {
        const int tr = (i + pr) >> 1;
        const int ra = (i + pr) & 1;
        if (tr < 128) {
            const int c0 = pr << 1;
            const int c1 = c0 | 1;
            float2 v = buf2[(((((c0 * BATCH + img_l) << 14) + (tr << 7) + jp) << 1) + ra)];
            s0 += v.x;
            s1 += v.y;
            const int base1 = (((c1 * BATCH + img_l) << 14) + (tr << 7)) << 2;
            s0 += buf[base1 + (jp << 2) + (ra << 1) + 1];
            if (jp < 127)
                s1 += buf[base1 + ((jp + 1) << 2) + (ra << 1)];
        }
    }
    reinterpret_cast<float2*>(out + ((size_t)(img0 + img_l) << 16) + (i << 8))[jp] =
        make_float2(s0, s1);

    __syncthreads();   // all block reads done before zeroing owned region

    // A) copies 0,1: full float4 tile-row bx
    {
        const int pc = t >> 7;
        const int tc = t & 127;
        reinterpret_cast<float4*>(buf)[((pc * BATCH + img_l) << 14) + (bx << 7) + tc] =
            make_float4(0.f, 0.f, 0.f, 0.f);
    }
    // B) copies 2,3: hi half of tile-row bx, lo half of tile-row bx+1
    {
        const int c  = 2 + (t >> 7);
        const int tc = t & 127;
        const int rowbase = ((((c * BATCH + img_l) << 14) + (bx << 7) + tc) << 1);
        float2* b2 = reinterpret_cast<float2*>(buf);
        b2[rowbase + 1] = make_float2(0.f, 0.f);
        if (bx < 127)
            b2[rowbase + (128 << 1)] = make_float2(0.f, 0.f);
    }

    // per-image max (values >= 0: uint bits monotonic)
    float m = fmaxf(s0, s1);
    #pragma unroll
    for (int o = 16; o > 0; o >>= 1)
        m = fmaxf(m, __shfl_xor_sync(0xFFFFFFFFu, m, o));
    __shared__ float sm[8];
    if ((t & 31) == 0) sm[t >> 5] = m;
    __syncthreads();
    if (t < 8) {
        m = sm[t];
        #pragma unroll
        for (int o = 4; o > 0; o >>= 1)
            m = fmaxf(m, __shfl_xor_sync(0xFFu, m, o));
        if (t == 0)
            atomicMax(&g_vmax_u[img0 + img_l], __float_as_uint(m));
    }
}

// ---------------------------------------------------------------------------
// Kernels
// ---------------------------------------------------------------------------
__global__ void __launch_bounds__(256) k_hist(const float* __restrict__ X,
                                              int img0, int bufi) {
    if (blockIdx.x == 0 && threadIdx.x < NIMG)   // first launch resets vmax
        g_vmax_u[threadIdx.x] = 0u;
    hist_block(X, g_buf[bufi], img0, blockIdx.x);
}

// 3072 blocks: bid%3==0 -> hist(b+1) [1024], else merge(b) [2048]
__global__ void __launch_bounds__(256) k_mixed(const float* __restrict__ X,
                                               float* __restrict__ out,
                                               int himg0, int hbufi,
                                               int mimg0, int mbufi) {
    const int bid = blockIdx.x;
    const int r3  = bid % 3;
    if (r3 == 0) {
        hist_block(X, g_buf[hbufi], himg0, bid / 3);
    } else {
        merge_block(g_buf[mbufi], out, mimg0, (bid / 3) * 2 + (r3 - 1));
    }
}

__global__ void __launch_bounds__(256) k_merge(float* __restrict__ out,
                                               int img0, int bufi) {
    merge_block(g_buf[bufi], out, img0, blockIdx.x);
}

__global__ void __launch_bounds__(256) k_norm(float* __restrict__ out) {
    const int img = blockIdx.y;
    const float inv = 1.0f / __uint_as_float(g_vmax_u[img]);
    float4* __restrict__ h4 = reinterpret_cast<float4*>(out + ((size_t)img << 16));
    const int i = blockIdx.x * blockDim.x + threadIdx.x;
    float4 v = h4[i];
    v.x *= inv; v.y *= inv; v.z *= inv; v.w *= inv;
    h4[i] = v;
}

// ---------------------------------------------------------------------------
extern "C" void kernel_launch(void* const* d_in, const int* in_sizes, int n_in,
                              void* d_out, int out_size) {
    const float* X = (const float*)d_in[0];
    float* out = (float*)d_out;

    // software pipeline: hist(b+1) overlapped with merge(b)
    k_hist<<<HB_PER_BATCH, 256>>>(X, 0, 0);
    for (int b = 1; b < NIMG / BATCH; ++b) {
        k_mixed<<<HB_PER_BATCH + MB_PER_BATCH, 256>>>(
            X, out, b * BATCH, b & 1, (b - 1) * BATCH, (b - 1) & 1);
    }
    k_merge<<<MB_PER_BATCH, 256>>>(out, NIMG - BATCH, (NIMG / BATCH - 1) & 1);

    dim3 ngrid((NBINS * NBINS / 4) / 256, NIMG);
    k_norm<<<ngrid, 256>>>(out);
}

// round 10
// speedup vs baseline: 1.1571x; 1.1571x over previous
#include <cuda_runtime.h>
#include <cuda_fp16.h>
#include <cuda_bf16.h>

#define NBINS 256
#define NIMG  96
#define BATCH 32            // 3 batches
#define HDIM  512
#define WDIM  512
#define CHUNK 16
#define PI_F  3.14159265358979323846f

// scratch: 4 parity copies x BATCH imgs x 128x128 tiles, cell = 4 x fp16 = 8B
// (2 uint32 words). 16.8 MB total. Zero-initialized at load; merge restores
// owned regions to zero each call (coalesced stores) -> graph-replay safe.
#define BUF_WORDS (4 * BATCH * 128 * 128 * 2)
__device__ unsigned g_buf[BUF_WORDS];
__device__ unsigned g_vmax_u[NIMG];

__device__ __forceinline__ void red_h4(unsigned* a, unsigned u0, unsigned u1) {
    asm volatile("red.global.add.noftz.v2.f16x2 [%0], {%1,%2};"
                 :: "l"(a), "r"(u0), "r"(u1) : "memory");
}

// ---------------------------------------------------------------------------
// Kernel 1: soft co-occurrence scatter, ONE 8B fp16 red per pixel pair.
// Parity copy c = (ia&1)*2 + (ib&1); tile (tr,tc) = ((ia+1)>>1, (ib+1)>>1).
// Cell half lanes: {wa0wb0, wa0wb1, wa1wb0, wa1wb1}.
// grid = (2, 32, BATCH), block = 256
// ---------------------------------------------------------------------------
__global__ void __launch_bounds__(256) k_hist(const float* __restrict__ X,
                                              int img0, int zero_vmax) {
    if (zero_vmax && blockIdx.x == 0 && blockIdx.y == 0 && blockIdx.z == 0 &&
        threadIdx.x < NIMG)
        g_vmax_u[threadIdx.x] = 0u;

    const int img_l = blockIdx.z;
    const int col   = blockIdx.x * blockDim.x + threadIdx.x;
    const int r0    = blockIdx.y * CHUNK;

    const float* __restrict__ base =
        X + (size_t)(img0 + img_l) * (HDIM * WDIM) + col;

    float a  = __ldg(base + (size_t)r0 * WDIM);
    float fa = fminf(floorf(a), 254.0f);
    int   ia = (int)fa;
    float wa0 = 0.5f * (1.0f + __cosf(PI_F * (a - fa)));

    const int rmax = min(r0 + CHUNK, HDIM - 1);
    for (int r = r0; r < rmax; ++r) {
        float b  = __ldg(base + (size_t)(r + 1) * WDIM);
        float fb = fminf(floorf(b), 254.0f);
        int   ib = (int)fb;
        float wb0 = 0.5f * (1.0f + __cosf(PI_F * (b - fb)));

        const float wa1 = 1.0f - wa0;
        const float wb1 = 1.0f - wb0;

        const int c  = ((ia & 1) << 1) | (ib & 1);
        const int tr = (ia + 1) >> 1;
        const int tc = (ib + 1) >> 1;
        unsigned* p = g_buf + ((((c * BATCH + img_l) << 14) + (tr << 7) + tc) << 1);

        __half2 h0 = __floats2half2_rn(wa0 * wb0, wa0 * wb1);  // lanes 0,1
        __half2 h1 = __floats2half2_rn(wa1 * wb0, wa1 * wb1);  // lanes 2,3
        red_h4(p, reinterpret_cast<unsigned&>(h0), reinterpret_cast<unsigned&>(h1));

        a = b; ia = ib; wa0 = wb0;
    }
}

// ---------------------------------------------------------------------------
// Kernel 2: merge + self-zero + per-image max. 256 threads, 2 bins/thread.
// Block bx -> output rows i = 2bx, 2bx+1. Thread t: di=t>>7, jp=t&127;
// bins (i, 2jp), (i, 2jp+1).
// Per row-parity pr (tr=(i+pr)>>1, ra=(i+pr)&1):
//   copy pr*2   cell (tr,jp)  word ra      -> half2 feeds both bins
//   copy pr*2+1 cell (tr,jp)  word ra hi   -> bin 2jp
//   copy pr*2+1 cell (tr,jp+1) word ra lo  -> bin 2jp+1
// Zero ownership (exclusive to block bx): copies 0,1 full cell-row bx
// (uint2); copies 2,3 word1 of row bx + word0 of row bx+1 (u32).
// grid = (128, BATCH), block = 256
// ---------------------------------------------------------------------------
__global__ void __launch_bounds__(256) k_merge(float* __restrict__ out,
                                               int img0) {
    const int img_l = blockIdx.y;
    const int bx    = blockIdx.x;
    const int t     = threadIdx.x;
    const int di    = t >> 7;
    const int jp    = t & 127;
    const int i     = (bx << 1) + di;

    float s0 = 0.0f, s1 = 0.0f;
    #pragma unroll
    for (int pr = 0; pr < 2; ++pr) {
        const int tr = (i + pr) >> 1;
        const int ra = (i + pr) & 1;
        if (tr < 128) {
            const int c0 = pr << 1;
            const int c1 = c0 | 1;
            const int cb0 = (((c0 * BATCH + img_l) << 14) + (tr << 7)) << 1;
            const int cb1 = (((c1 * BATCH + img_l) << 14) + (tr << 7)) << 1;

            unsigned w = g_buf[cb0 + (jp << 1) + ra];
            float2 v = __half22float2(reinterpret_cast<__half2&>(w));
            s0 += v.x;
            s1 += v.y;

            unsigned wA = g_buf[cb1 + (jp << 1) + ra];
            s0 += __high2float(reinterpret_cast<__half2&>(wA));
            if (jp < 127) {
                unsigned wB = g_buf[cb1 + ((jp + 1) << 1) + ra];
                s1 += __low2float(reinterpret_cast<__half2&>(wB));
            }
        }
    }
    reinterpret_cast<float2*>(out + ((size_t)(img0 + img_l) << 16) + (i << 8))[jp] =
        make_float2(s0, s1);

    __syncthreads();   // all block reads done before zeroing owned region

    // A) copies 0,1: full cell-row bx (8B uint2 store per thread)
    {
        const int pc = t >> 7;
        const int tc = t & 127;
        reinterpret_cast<uint2*>(g_buf)[((pc * BATCH + img_l) << 14) + (bx << 7) + tc] =
            make_uint2(0u, 0u);
    }
    // B) copies 2,3: word1 of row bx, word0 of row bx+1
    {
        const int c  = 2 + (t >> 7);
        const int tc = t & 127;
        const int wb = ((((c * BATCH + img_l) << 14) + (bx << 7) + tc) << 1);
        g_buf[wb + 1] = 0u;
        if (bx < 127)
            g_buf[wb + 256] = 0u;    // cell (bx+1, tc), word 0
    }

    // per-image max (values >= 0: uint bits monotonic)
    float m = fmaxf(s0, s1);
    #pragma unroll
    for (int o = 16; o > 0; o >>= 1)
        m = fmaxf(m, __shfl_xor_sync(0xFFFFFFFFu, m, o));
    __shared__ float sm[8];
    if ((t & 31) == 0) sm[t >> 5] = m;
    __syncthreads();
    if (t < 8) {
        m = sm[t];
        #pragma unroll
        for (int o = 4; o > 0; o >>= 1)
            m = fmaxf(m, __shfl_xor_sync(0xFFu, m, o));
        if (t == 0)
            atomicMax(&g_vmax_u[img0 + img_l], __float_as_uint(m));
    }
}

// ---------------------------------------------------------------------------
// Kernel 3: scale each histogram by 1/vmax.  grid = (64, NIMG)
// ---------------------------------------------------------------------------
__global__ void __launch_bounds__(256) k_norm(float* __restrict__ out) {
    const int img = blockIdx.y;
    const float inv = 1.0f / __uint_as_float(g_vmax_u[img]);
    float4* __restrict__ h4 = reinterpret_cast<float4*>(out + ((size_t)img << 16));
    const int i = blockIdx.x * blockDim.x + threadIdx.x;   // [0, 16384)
    float4 v = h4[i];
    v.x *= inv; v.y *= inv; v.z *= inv; v.w *= inv;
    h4[i] = v;
}

// ---------------------------------------------------------------------------
extern "C" void kernel_launch(void* const* d_in, const int* in_sizes, int n_in,
                              void* d_out, int out_size) {
    const float* X = (const float*)d_in[0];
    float* out = (float*)d_out;

    const dim3 hgrid(WDIM / 256, (HDIM - 1 + CHUNK - 1) / CHUNK, BATCH);
    const dim3 mgrid(128, BATCH);

    for (int b = 0; b < NIMG / BATCH; ++b) {
        k_hist <<<hgrid, 256>>>(X, b * BATCH, b == 0);
        k_merge<<<mgrid, 256>>>(out, b * BATCH);
    }

    dim3 ngrid((NBINS * NBINS / 4) / 256, NIMG);
    k_norm<<<ngrid, 256>>>(out);
}

// round 11
// speedup vs baseline: 1.2437x; 1.0748x over previous
#include <cuda_runtime.h>
#include <cuda_fp16.h>
#include <cuda_bf16.h>

#define NBINS 256
#define NIMG  96
#define BATCH 96            // single batch: scratch 50.3 MB, L2-resident
#define HDIM  512
#define WDIM  512
#define CHUNK 16
#define PI_F  3.14159265358979323846f

// scratch: 4 parity copies x 96 imgs x 128x128 tiles, cell = 4 x fp16 = 8B.
// Zero-initialized at load; merge restores owned regions to zero each call
// (block-exclusive coalesced stores) -> graph-replay safe.
#define BUF_WORDS (4 * BATCH * 128 * 128 * 2)
__device__ unsigned g_buf[BUF_WORDS];
__device__ unsigned g_vmax_u[NIMG];

__device__ __forceinline__ void red_h4(unsigned* a, unsigned u0, unsigned u1) {
    asm volatile("red.global.add.noftz.v2.f16x2 [%0], {%1,%2};"
                 :: "l"(a), "r"(u0), "r"(u1) : "memory");
}

// ---------------------------------------------------------------------------
// Kernel 1: soft co-occurrence scatter, ONE 8B fp16 red per pixel pair.
// Parity copy c = (ia&1)*2 + (ib&1); tile (tr,tc) = ((ia+1)>>1, (ib+1)>>1).
// Cell half lanes: {wa0wb0, wa0wb1 | wa1wb0, wa1wb1} (word = row-half).
// grid = (2, 32, 96), block = 256
// ---------------------------------------------------------------------------
__global__ void __launch_bounds__(256) k_hist(const float* __restrict__ X) {
    if (blockIdx.x == 0 && blockIdx.y == 0 && blockIdx.z == 0 &&
        threadIdx.x < NIMG)
        g_vmax_u[threadIdx.x] = 0u;

    const int img = blockIdx.z;
    const int col = blockIdx.x * blockDim.x + threadIdx.x;
    const int r0  = blockIdx.y * CHUNK;

    const float* __restrict__ base = X + (size_t)img * (HDIM * WDIM) + col;

    float a  = __ldg(base + (size_t)r0 * WDIM);
    float fa = fminf(floorf(a), 254.0f);
    int   ia = (int)fa;
    float wa0 = 0.5f * (1.0f + __cosf(PI_F * (a - fa)));

    const int rmax = min(r0 + CHUNK, HDIM - 1);
    for (int r = r0; r < rmax; ++r) {
        float b  = __ldg(base + (size_t)(r + 1) * WDIM);
        float fb = fminf(floorf(b), 254.0f);
        int   ib = (int)fb;
        float wb0 = 0.5f * (1.0f + __cosf(PI_F * (b - fb)));

        const float wa1 = 1.0f - wa0;
        const float wb1 = 1.0f - wb0;

        const int c  = ((ia & 1) << 1) | (ib & 1);
        const int tr = (ia + 1) >> 1;
        const int tc = (ib + 1) >> 1;
        unsigned* p = g_buf + ((((c * BATCH + img) << 14) + (tr << 7) + tc) << 1);

        __half2 h0 = __floats2half2_rn(wa0 * wb0, wa0 * wb1);
        __half2 h1 = __floats2half2_rn(wa1 * wb0, wa1 * wb1);
        red_h4(p, reinterpret_cast<unsigned&>(h0), reinterpret_cast<unsigned&>(h1));

        a = b; ia = ib; wa0 = wb0;
    }
}

// ---------------------------------------------------------------------------
// Kernel 2: merge + self-zero + per-image max. 256 threads, 2 bins/thread.
// Block bx -> output rows i = 2bx, 2bx+1. Thread t: di=t>>7, jp=t&127;
// bins (i, 2jp), (i, 2jp+1). All scratch reads are coalesced uint2
// full-cell loads (consecutive jp -> consecutive cells); needed halves
// extracted in registers.
// Zero ownership (exclusive to block bx): copies 0,1 full cell-row bx
// (uint2); copies 2,3 word1 of row bx + word0 of row bx+1.
// grid = (128, 96), block = 256
// ---------------------------------------------------------------------------
__global__ void __launch_bounds__(256) k_merge(float* __restrict__ out) {
    const int img = blockIdx.y;
    const int bx  = blockIdx.x;
    const int t   = threadIdx.x;
    const int di  = t >> 7;
    const int jp  = t & 127;
    const int i   = (bx << 1) + di;

    const uint2* __restrict__ buf2 = reinterpret_cast<const uint2*>(g_buf);

    float s0 = 0.0f, s1 = 0.0f;
    #pragma unroll
    for (int pr = 0; pr < 2; ++pr) {
        const int tr = (i + pr) >> 1;
        const int ra = (i + pr) & 1;
        if (tr < 128) {
            const int c0 = pr << 1;
            const int c1 = c0 | 1;
            const int cb0 = ((c0 * BATCH + img) << 14) + (tr << 7);
            const int cb1 = ((c1 * BATCH + img) << 14) + (tr << 7);

            // copy c0, cell (tr,jp): word ra feeds both bins
            uint2 u0 = buf2[cb0 + jp];
            unsigned w = ra ? u0.y : u0.x;
            float2 v = __half22float2(reinterpret_cast<__half2&>(w));
            s0 += v.x;
            s1 += v.y;

            // copy c1, cell (tr,jp): hi of word ra -> bin 2jp
            uint2 uA = buf2[cb1 + jp];
            unsigned wA = ra ? uA.y : uA.x;
            s0 += __high2float(reinterpret_cast<__half2&>(wA));

            // copy c1, cell (tr,jp+1): lo of word ra -> bin 2jp+1
            if (jp < 127) {
                uint2 uB = buf2[cb1 + jp + 1];
                unsigned wB = ra ? uB.y : uB.x;
                s1 += __low2float(reinterpret_cast<__half2&>(wB));
            }
        }
    }
    reinterpret_cast<float2*>(out + ((size_t)img << 16) + (i << 8))[jp] =
        make_float2(s0, s1);

    __syncthreads();   // all block reads done before zeroing owned region

    // A) copies 0,1: full cell-row bx (uint2 store per thread)
    {
        const int pc = t >> 7;
        const int tc = t & 127;
        reinterpret_cast<uint2*>(g_buf)[((pc * BATCH + img) << 14) + (bx << 7) + tc] =
            make_uint2(0u, 0u);
    }
    // B) copies 2,3: word1 of row bx, word0 of row bx+1
    {
        const int c  = 2 + (t >> 7);
        const int tc = t & 127;
        const int wb = ((((c * BATCH + img) << 14) + (bx << 7) + tc) << 1);
        g_buf[wb + 1] = 0u;
        if (bx < 127)
            g_buf[wb + 256] = 0u;    // cell (bx+1, tc), word 0
    }

    // per-image max (values >= 0: uint bits monotonic)
    float m = fmaxf(s0, s1);
    #pragma unroll
    for (int o = 16; o > 0; o >>= 1)
        m = fmaxf(m, __shfl_xor_sync(0xFFFFFFFFu, m, o));
    __shared__ float sm[8];
    if ((t & 31) == 0) sm[t >> 5] = m;
    __syncthreads();
    if (t < 8) {
        m = sm[t];
        #pragma unroll
        for (int o = 4; o > 0; o >>= 1)
            m = fmaxf(m, __shfl_xor_sync(0xFFu, m, o));
        if (t == 0)
            atomicMax(&g_vmax_u[img], __float_as_uint(m));
    }
}

// ---------------------------------------------------------------------------
// Kernel 3: scale each histogram by 1/vmax.  grid = (64, NIMG)
// ---------------------------------------------------------------------------
__global__ void __launch_bounds__(256) k_norm(float* __restrict__ out) {
    const int img = blockIdx.y;
    const float inv = 1.0f / __uint_as_float(g_vmax_u[img]);
    float4* __restrict__ h4 = reinterpret_cast<float4*>(out + ((size_t)img << 16));
    const int i = blockIdx.x * blockDim.x + threadIdx.x;   // [0, 16384)
    float4 v = h4[i];
    v.x *= inv; v.y *= inv; v.z *= inv; v.w *= inv;
    h4[i] = v;
}

// ---------------------------------------------------------------------------
extern "C" void kernel_launch(void* const* d_in, const int* in_sizes, int n_in,
                              void* d_out, int out_size) {
    const float* X = (const float*)d_in[0];
    float* out = (float*)d_out;

    const dim3 hgrid(WDIM / 256, (HDIM - 1 + CHUNK - 1) / CHUNK, NIMG);
    const dim3 mgrid(128, NIMG);

    k_hist <<<hgrid, 256>>>(X);
    k_merge<<<mgrid, 256>>>(out);

    dim3 ngrid((NBINS * NBINS / 4) / 256, NIMG);
    k_norm<<<ngrid, 256>>>(out);
}